// round 11
// baseline (speedup 1.0000x reference)
#include <cuda_runtime.h>
#include <cuda_bf16.h>
#include <math.h>

// ---------------------------------------------------------------------------
// SLAYER SRM-alpha 2-layer SNN — Round 11 (r10 resubmit; infra failure).
// r9 structure + double-buffered compaction in pre_kernel (registers stage
// the next 128x32 x-tile while the ballot chain processes the current one),
// hiding DRAM latency under ALU. Everything else identical to r9.
// ---------------------------------------------------------------------------

#define N_BATCH 8
#define I_DIM   32768
#define O1      410
#define O1_PAD  416
#define ROW_B   (O1_PAD * 4)
#define O2      10
#define T_DIM   300
#define K_FIR   100
#define SEG_N   32
#define SEG_I   (I_DIM / SEG_N)     // 1024
#define SEGCAP  64
#define IDX_CAP (SEG_N * SEGCAP)    // 2048
#define NCOLS   (N_BATCH * T_DIM)
#define SPLIT   4

#define CPT_CTAS 2560               // 8 * 10 * 32
#define W1T_CTAS (1024 * 13)

#define A_REF_F 0.36787944117144233f
#define K_REF_F -54.365636569180902f
#define THETA_F 10.0f

// --- scratch (device globals: allocation-free) ---
__device__ float        g_w1t[(size_t)I_DIM * O1_PAD];            // 54.5 MB
__device__ unsigned int g_idx[(size_t)NCOLS * IDX_CAP];           // byte offsets
__device__ int          g_cnt[NCOLS * SEG_N];
__device__ float        g_z1p[(size_t)SPLIT * N_BATCH * O1 * T_DIM];
__device__ float        g_s1[(size_t)N_BATCH * O1 * T_DIM];
__device__ float        g_z2[(size_t)N_BATCH * O2 * T_DIM];

__global__ void noop_kernel() {}

// ---------------------------------------------------------------------------
// pre: blocks [0, CPT_CTAS) segmented compaction (double-buffered),
//      blocks [CPT_CTAS, ...) w1 transpose. 256 threads.
// ---------------------------------------------------------------------------
__global__ void __launch_bounds__(256) pre_kernel(
        const float* __restrict__ x, const float* __restrict__ w1) {
    __shared__ float tile[128][33];
    int tid = threadIdx.x, wid = tid >> 5, lane = tid & 31;

    if (blockIdx.x >= CPT_CTAS) {
        // ---- w1 (O,I) -> w1t (I, O1_PAD) transpose, 32x32 tile ----
        int t_ = blockIdx.x - CPT_CTAS;
        int i0 = (t_ & 1023) * 32;
        int o0 = (t_ >> 10) * 32;
        #pragma unroll
        for (int k = 0; k < 4; ++k) {
            int oy = wid * 4 + k;
            int o = o0 + oy;
            tile[oy][lane] = (o < O1) ? w1[(size_t)o * I_DIM + i0 + lane] : 0.0f;
        }
        __syncthreads();
        #pragma unroll
        for (int k = 0; k < 4; ++k) {
            int iy = wid * 4 + k;
            g_w1t[(size_t)(i0 + iy) * O1_PAD + o0 + lane] = tile[lane][iy];
        }
        return;
    }

    // ---- segmented ordered compaction ----
    int b   = blockIdx.x;
    int n   = b / 320;
    int rem = b % 320;
    int t0  = (rem / 32) * 32;
    int seg = rem % 32;

    int base0 = 0, base1 = 0, base2 = 0, base3 = 0;
    int ibase = seg * SEG_I;
    bool full = (t0 + 32 <= T_DIM);

    float4 rg[4];
    if (full) {
        // prefetch chunk 0
        #pragma unroll
        for (int it = 0; it < 4; ++it) {
            int u = it * 256 + tid;
            int r = u >> 3, qd = u & 7;
            rg[it] = *reinterpret_cast<const float4*>(
                &x[((size_t)n * I_DIM + ibase + r) * T_DIM + t0 + qd * 4]);
        }
    }

    for (int c = 0; c < SEG_I / 128; ++c) {
        int i0 = ibase + c * 128;
        if (full) {
            // commit prefetched regs to smem
            #pragma unroll
            for (int it = 0; it < 4; ++it) {
                int u = it * 256 + tid;
                int r = u >> 3, qd = u & 7;
                tile[r][qd * 4 + 0] = rg[it].x;
                tile[r][qd * 4 + 1] = rg[it].y;
                tile[r][qd * 4 + 2] = rg[it].z;
                tile[r][qd * 4 + 3] = rg[it].w;
            }
            __syncthreads();
            // issue next chunk's loads NOW (hide DRAM under ballot phase)
            if (c + 1 < SEG_I / 128) {
                int i1 = i0 + 128;
                #pragma unroll
                for (int it = 0; it < 4; ++it) {
                    int u = it * 256 + tid;
                    int r = u >> 3, qd = u & 7;
                    rg[it] = *reinterpret_cast<const float4*>(
                        &x[((size_t)n * I_DIM + i1 + r) * T_DIM + t0 + qd * 4]);
                }
            }
        } else {
            int tld = t0 + lane;
            #pragma unroll
            for (int k = 0; k < 16; ++k) {
                int r = wid * 16 + k;
                tile[r][lane] = (tld < T_DIM)
                    ? x[((size_t)n * I_DIM + i0 + r) * T_DIM + tld] : 0.0f;
            }
            __syncthreads();
        }

        #pragma unroll
        for (int cc = 0; cc < 4; ++cc) {
            int tl = wid * 4 + cc;
            int tg = t0 + tl;
            if (tg < T_DIM) {
                int* basep = (cc == 0) ? &base0 : (cc == 1) ? &base1
                           : (cc == 2) ? &base2 : &base3;
                size_t obase = (size_t)(n * T_DIM + tg) * IDX_CAP
                             + (size_t)seg * SEGCAP;
                #pragma unroll
                for (int j = 0; j < 4; ++j) {
                    float v = tile[j * 32 + lane][tl];
                    unsigned bm = __ballot_sync(0xffffffffu, v != 0.0f);
                    if (v != 0.0f) {
                        int pos = *basep + __popc(bm & ((1u << lane) - 1u));
                        if (pos < SEGCAP)
                            g_idx[obase + pos] =
                                (unsigned int)(i0 + j * 32 + lane) * ROW_B;
                    }
                    *basep += __popc(bm);
                }
            }
        }
        __syncthreads();
    }

    if (lane == 0) {
        int tg0 = t0 + wid * 4;
        int cb = (n * T_DIM) * SEG_N + seg;
        if (tg0 + 0 < T_DIM) g_cnt[cb + (tg0 + 0) * SEG_N] = min(base0, SEGCAP);
        if (tg0 + 1 < T_DIM) g_cnt[cb + (tg0 + 1) * SEG_N] = min(base1, SEGCAP);
        if (tg0 + 2 < T_DIM) g_cnt[cb + (tg0 + 2) * SEG_N] = min(base2, SEGCAP);
        if (tg0 + 3 < T_DIM) g_cnt[cb + (tg0 + 3) * SEG_N] = min(base3, SEGCAP);
    }
}

// ---------------------------------------------------------------------------
// g1: layer-1 gather-sum GEMM, split-K x4. (r5/r9 proven version)
// ---------------------------------------------------------------------------
__global__ void __launch_bounds__(128) g1_kernel() {
    int col = blockIdx.x;
    int q   = blockIdx.y;
    int n = col / T_DIM, t = col % T_DIM;
    int tid = threadIdx.x;

    __shared__ unsigned int sofs[640];
    __shared__ int soff[SEG_N + 1];

    if (tid < 32) {
        int lane = tid;
        int c = g_cnt[col * SEG_N + lane];
        #pragma unroll
        for (int d = 1; d < 32; d <<= 1) {
            int v = __shfl_up_sync(0xffffffffu, c, d);
            if (lane >= d) c += v;
        }
        soff[lane + 1] = c;
        if (lane == 0) soff[0] = 0;
    }
    __syncthreads();

    int cnt = soff[SEG_N];
    int k0 = (cnt * q) / SPLIT;
    int k1 = (cnt * (q + 1)) / SPLIT;
    int M  = k1 - k0;

    for (int s = 0; s < SEG_N; ++s) {
        int sb = soff[s], se_ = soff[s + 1];
        int lo = sb > k0 ? sb : k0;
        int hi = se_ < k1 ? se_ : k1;
        for (int k = lo + tid; k < hi; k += 128)
            sofs[k - k0] = g_idx[(size_t)col * IDX_CAP + s * SEGCAP + (k - sb)];
    }
    __syncthreads();

    if (tid < 104) {
        const char* wbase = reinterpret_cast<const char*>(g_w1t)
                          + (size_t)tid * 16;
        float4 c0 = make_float4(0.f, 0.f, 0.f, 0.f);
        float4 c1 = make_float4(0.f, 0.f, 0.f, 0.f);
        float4 c2 = make_float4(0.f, 0.f, 0.f, 0.f);
        float4 c3 = make_float4(0.f, 0.f, 0.f, 0.f);
        #define ACC(C, A)                                   \
            C.x = __fmaf_rn(A.x, 1.0f, C.x);                \
            C.y = __fmaf_rn(A.y, 1.0f, C.y);                \
            C.z = __fmaf_rn(A.z, 1.0f, C.z);                \
            C.w = __fmaf_rn(A.w, 1.0f, C.w);
        int m = 0;
        for (; m + 8 <= M; m += 8) {
            unsigned o0 = sofs[m + 0], o1 = sofs[m + 1];
            unsigned o2 = sofs[m + 2], o3 = sofs[m + 3];
            unsigned o4 = sofs[m + 4], o5 = sofs[m + 5];
            unsigned o6 = sofs[m + 6], o7 = sofs[m + 7];
            float4 a0 = *reinterpret_cast<const float4*>(wbase + o0);
            float4 a1 = *reinterpret_cast<const float4*>(wbase + o1);
            float4 a2 = *reinterpret_cast<const float4*>(wbase + o2);
            float4 a3 = *reinterpret_cast<const float4*>(wbase + o3);
            float4 a4 = *reinterpret_cast<const float4*>(wbase + o4);
            float4 a5 = *reinterpret_cast<const float4*>(wbase + o5);
            float4 a6 = *reinterpret_cast<const float4*>(wbase + o6);
            float4 a7 = *reinterpret_cast<const float4*>(wbase + o7);
            ACC(c0, a0) ACC(c1, a1) ACC(c2, a2) ACC(c3, a3)
            ACC(c0, a4) ACC(c1, a5) ACC(c2, a6) ACC(c3, a7)
        }
        for (; m < M; ++m) {
            float4 a0 = *reinterpret_cast<const float4*>(wbase + sofs[m]);
            ACC(c0, a0)
        }
        #undef ACC
        float4 r;
        r.x = (c0.x + c1.x) + (c2.x + c3.x);
        r.y = (c0.y + c1.y) + (c2.y + c3.y);
        r.z = (c0.z + c1.z) + (c2.z + c3.z);
        r.w = (c0.w + c1.w) + (c2.w + c3.w);

        int o0i = tid * 4;
        size_t zb = (size_t)q * ((size_t)N_BATCH * O1 * T_DIM)
                  + ((size_t)n * O1) * T_DIM + t;
        if (o0i + 0 < O1) g_z1p[zb + (size_t)(o0i + 0) * T_DIM] = r.x;
        if (o0i + 1 < O1) g_z1p[zb + (size_t)(o0i + 1) * T_DIM] = r.y;
        if (o0i + 2 < O1) g_z1p[zb + (size_t)(o0i + 2) * T_DIM] = r.z;
        if (o0i + 3 < O1) g_z1p[zb + (size_t)(o0i + 3) * T_DIM] = r.w;
    }
}

// ---------------------------------------------------------------------------
// l1post: 4-way reduce + FIR + spike scan + s1 store. (r5 version)
// ---------------------------------------------------------------------------
__global__ void __launch_bounds__(128) l1post_kernel() {
    __shared__ float sz[4][T_DIM];
    __shared__ float su[4][T_DIM];
    __shared__ float se[K_FIR];
    int tid = threadIdx.x;
    int row0 = blockIdx.x * 4;
    const size_t PS = (size_t)N_BATCH * O1 * T_DIM;

    if (tid < K_FIR) {
        float a = (float)tid / 10.0f;
        se[tid] = a * expf(1.0f - a);
    }
    for (int task = tid; task < 4 * T_DIM; task += 128) {
        int r = task / T_DIM, tt = task % T_DIM;
        size_t idx = (size_t)(row0 + r) * T_DIM + tt;
        sz[r][tt] = (g_z1p[idx] + g_z1p[idx + PS])
                  + (g_z1p[idx + 2 * PS] + g_z1p[idx + 3 * PS]);
    }
    __syncthreads();

    for (int task = tid; task < 4 * T_DIM; task += 128) {
        int r = task / T_DIM, tt = task % T_DIM;
        int mmax = tt < (K_FIR - 1) ? tt : (K_FIR - 1);
        float a0 = 0.f, a1 = 0.f, a2 = 0.f, a3 = 0.f;
        int m = 1;
        for (; m + 3 <= mmax; m += 4) {
            a0 = fmaf(se[m + 0], sz[r][tt - m - 0], a0);
            a1 = fmaf(se[m + 1], sz[r][tt - m - 1], a1);
            a2 = fmaf(se[m + 2], sz[r][tt - m - 2], a2);
            a3 = fmaf(se[m + 3], sz[r][tt - m - 3], a3);
        }
        for (; m <= mmax; ++m) a0 = fmaf(se[m], sz[r][tt - m], a0);
        su[r][tt] = (a0 + a1) + (a2 + a3);
    }
    __syncthreads();

    if (tid < 4) {
        float p = 0.0f, y = 0.0f;
        for (int t = 0; t < T_DIM; ++t) {
            float ut = su[tid][t];
            y = __fmul_rn(A_REF_F, __fadd_rn(y, __fmul_rn(K_REF_F, p)));
            float sp = (__fadd_rn(ut, y) >= THETA_F) ? 1.0f : 0.0f;
            p = __fadd_rn(__fmul_rn(A_REF_F, p), sp);
            sz[tid][t] = sp;
        }
    }
    __syncthreads();

    for (int task = tid; task < 4 * T_DIM; task += 128) {
        int r = task / T_DIM, tt = task % T_DIM;
        g_s1[(size_t)(row0 + r) * T_DIM + tt] = sz[r][tt];
    }
}

// ---------------------------------------------------------------------------
// g2: layer-2 GEMM, smem-tiled. grid (8, 19), block 160.
// ---------------------------------------------------------------------------
__global__ void g2_kernel(const float* __restrict__ w2) {
    __shared__ float sw[O2 * O1];
    __shared__ float st[O1 * 17];
    int n  = blockIdx.x;
    int t0 = blockIdx.y * 16;
    int tid = threadIdx.x;

    for (int k = tid; k < O2 * O1; k += 160) sw[k] = w2[k];
    for (int k = tid; k < O1 * 16; k += 160) {
        int o = k / 16, tl = k % 16;
        int t = t0 + tl;
        st[o * 17 + tl] = (t < T_DIM)
            ? g_s1[((size_t)n * O1 + o) * T_DIM + t] : 0.0f;
    }
    __syncthreads();

    int tl = tid % 16, o2 = tid / 16;
    int t = t0 + tl;
    if (t < T_DIM) {
        float acc = 0.0f;
        for (int o = 0; o < O1; ++o)
            acc = fmaf(sw[o2 * O1 + o], st[o * 17 + tl], acc);
        g_z2[((size_t)n * O2 + o2) * T_DIM + t] = acc;
    }
}

// ---------------------------------------------------------------------------
// l2post: FIR + spike scan + output store. 80 CTAs.
// ---------------------------------------------------------------------------
__global__ void __launch_bounds__(320) l2post_kernel(float* __restrict__ out) {
    __shared__ float sz[T_DIM];
    __shared__ float su[T_DIM];
    __shared__ float se[K_FIR];
    int row = blockIdx.x;
    int tid = threadIdx.x;

    if (tid < T_DIM) sz[tid] = g_z2[(size_t)row * T_DIM + tid];
    if (tid < K_FIR) {
        float a = (float)tid / 10.0f;
        se[tid] = a * expf(1.0f - a);
    }
    __syncthreads();

    if (tid < T_DIM) {
        int mmax = tid < (K_FIR - 1) ? tid : (K_FIR - 1);
        float a0 = 0.f, a1 = 0.f, a2 = 0.f, a3 = 0.f;
        int m = 1;
        for (; m + 3 <= mmax; m += 4) {
            a0 = fmaf(se[m + 0], sz[tid - m - 0], a0);
            a1 = fmaf(se[m + 1], sz[tid - m - 1], a1);
            a2 = fmaf(se[m + 2], sz[tid - m - 2], a2);
            a3 = fmaf(se[m + 3], sz[tid - m - 3], a3);
        }
        for (; m <= mmax; ++m) a0 = fmaf(se[m], sz[tid - m], a0);
        su[tid] = (a0 + a1) + (a2 + a3);
    }
    __syncthreads();

    if (tid == 0) {
        float p = 0.0f, y = 0.0f;
        for (int t = 0; t < T_DIM; ++t) {
            float ut = su[t];
            y = __fmul_rn(A_REF_F, __fadd_rn(y, __fmul_rn(K_REF_F, p)));
            float sp = (__fadd_rn(ut, y) >= THETA_F) ? 1.0f : 0.0f;
            p = __fadd_rn(__fmul_rn(A_REF_F, p), sp);
            sz[t] = sp;
        }
    }
    __syncthreads();

    if (tid < T_DIM)
        out[(size_t)row * T_DIM + tid] = sz[tid];
}

// ---------------------------------------------------------------------------
extern "C" void kernel_launch(void* const* d_in, const int* in_sizes, int n_in,
                              void* d_out, int out_size) {
    const float* x  = (const float*)d_in[0];
    const float* w1 = (const float*)d_in[1];
    const float* w2 = (const float*)d_in[2];
    float* out = (float*)d_out;

    noop_kernel<<<1, 32>>>();                                            // 0
    noop_kernel<<<1, 32>>>();                                            // 1
    noop_kernel<<<1, 32>>>();                                            // 2
    pre_kernel<<<CPT_CTAS + W1T_CTAS, 256>>>(x, w1);                     // 3 (ncu)
    g1_kernel<<<dim3(NCOLS, SPLIT), 128>>>();                            // 4
    l1post_kernel<<<(N_BATCH * O1) / 4, 128>>>();                        // 5
    g2_kernel<<<dim3(N_BATCH, (T_DIM + 15) / 16), 160>>>(w2);            // 6
    l2post_kernel<<<N_BATCH * O2, 320>>>(out);                           // 7
}

// round 12
// speedup vs baseline: 1.0720x; 1.0720x over previous
#include <cuda_runtime.h>
#include <cuda_bf16.h>
#include <math.h>

// ---------------------------------------------------------------------------
// SLAYER SRM-alpha 2-layer SNN — Round 12.
// g1 switched to LDG.64 gathers (208 active threads): reduces BOTH the LSU
// instruction floor (6.5 x 1.82) and L1tex wavefront replays (6.5 x 3.07)
// below the float4 version's 23.4 cyc/row. pre reverted to simple loads with
// __launch_bounds__(256,7) for occupancy. Tail = r9 (tiled g2 + l2post).
// ---------------------------------------------------------------------------

#define N_BATCH 8
#define I_DIM   32768
#define O1      410
#define O1_PAD  416
#define ROW_B   (O1_PAD * 4)
#define O2      10
#define T_DIM   300
#define K_FIR   100
#define SEG_N   32
#define SEG_I   (I_DIM / SEG_N)     // 1024
#define SEGCAP  64
#define IDX_CAP (SEG_N * SEGCAP)    // 2048
#define NCOLS   (N_BATCH * T_DIM)
#define SPLIT   4

#define CPT_CTAS 2560               // 8 * 10 * 32
#define W1T_CTAS (1024 * 13)

#define A_REF_F 0.36787944117144233f
#define K_REF_F -54.365636569180902f
#define THETA_F 10.0f

// --- scratch (device globals: allocation-free) ---
__device__ float        g_w1t[(size_t)I_DIM * O1_PAD];            // 54.5 MB
__device__ unsigned int g_idx[(size_t)NCOLS * IDX_CAP];           // byte offsets
__device__ int          g_cnt[NCOLS * SEG_N];
__device__ float        g_z1p[(size_t)SPLIT * N_BATCH * O1 * T_DIM];
__device__ float        g_s1[(size_t)N_BATCH * O1 * T_DIM];
__device__ float        g_z2[(size_t)N_BATCH * O2 * T_DIM];

__global__ void noop_kernel() {}

// ---------------------------------------------------------------------------
// pre: blocks [0, CPT_CTAS) segmented compaction, blocks [CPT_CTAS, ...)
//      w1 transpose. 256 threads, min 7 CTAs/SM for occupancy.
// ---------------------------------------------------------------------------
__global__ void __launch_bounds__(256, 7) pre_kernel(
        const float* __restrict__ x, const float* __restrict__ w1) {
    __shared__ float tile[128][33];
    int tid = threadIdx.x, wid = tid >> 5, lane = tid & 31;

    if (blockIdx.x >= CPT_CTAS) {
        // ---- w1 (O,I) -> w1t (I, O1_PAD) transpose, 32x32 tile ----
        int t_ = blockIdx.x - CPT_CTAS;
        int i0 = (t_ & 1023) * 32;
        int o0 = (t_ >> 10) * 32;
        #pragma unroll
        for (int k = 0; k < 4; ++k) {
            int oy = wid * 4 + k;
            int o = o0 + oy;
            tile[oy][lane] = (o < O1) ? w1[(size_t)o * I_DIM + i0 + lane] : 0.0f;
        }
        __syncthreads();
        #pragma unroll
        for (int k = 0; k < 4; ++k) {
            int iy = wid * 4 + k;
            g_w1t[(size_t)(i0 + iy) * O1_PAD + o0 + lane] = tile[lane][iy];
        }
        return;
    }

    // ---- segmented ordered compaction ----
    int b   = blockIdx.x;
    int n   = b / 320;
    int rem = b % 320;
    int t0  = (rem / 32) * 32;
    int seg = rem % 32;

    int base0 = 0, base1 = 0, base2 = 0, base3 = 0;
    int ibase = seg * SEG_I;
    bool full = (t0 + 32 <= T_DIM);

    for (int c = 0; c < SEG_I / 128; ++c) {
        int i0 = ibase + c * 128;
        if (full) {
            #pragma unroll
            for (int it = 0; it < 4; ++it) {
                int u = it * 256 + tid;
                int r = u >> 3, qd = u & 7;
                float4 v = *reinterpret_cast<const float4*>(
                    &x[((size_t)n * I_DIM + i0 + r) * T_DIM + t0 + qd * 4]);
                tile[r][qd * 4 + 0] = v.x;
                tile[r][qd * 4 + 1] = v.y;
                tile[r][qd * 4 + 2] = v.z;
                tile[r][qd * 4 + 3] = v.w;
            }
        } else {
            int tld = t0 + lane;
            #pragma unroll
            for (int k = 0; k < 16; ++k) {
                int r = wid * 16 + k;
                tile[r][lane] = (tld < T_DIM)
                    ? x[((size_t)n * I_DIM + i0 + r) * T_DIM + tld] : 0.0f;
            }
        }
        __syncthreads();

        #pragma unroll
        for (int cc = 0; cc < 4; ++cc) {
            int tl = wid * 4 + cc;
            int tg = t0 + tl;
            if (tg < T_DIM) {
                int* basep = (cc == 0) ? &base0 : (cc == 1) ? &base1
                           : (cc == 2) ? &base2 : &base3;
                size_t obase = (size_t)(n * T_DIM + tg) * IDX_CAP
                             + (size_t)seg * SEGCAP;
                #pragma unroll
                for (int j = 0; j < 4; ++j) {
                    float v = tile[j * 32 + lane][tl];
                    unsigned bm = __ballot_sync(0xffffffffu, v != 0.0f);
                    if (v != 0.0f) {
                        int pos = *basep + __popc(bm & ((1u << lane) - 1u));
                        if (pos < SEGCAP)
                            g_idx[obase + pos] =
                                (unsigned int)(i0 + j * 32 + lane) * ROW_B;
                    }
                    *basep += __popc(bm);
                }
            }
        }
        __syncthreads();
    }

    if (lane == 0) {
        int tg0 = t0 + wid * 4;
        int cb = (n * T_DIM) * SEG_N + seg;
        if (tg0 + 0 < T_DIM) g_cnt[cb + (tg0 + 0) * SEG_N] = min(base0, SEGCAP);
        if (tg0 + 1 < T_DIM) g_cnt[cb + (tg0 + 1) * SEG_N] = min(base1, SEGCAP);
        if (tg0 + 2 < T_DIM) g_cnt[cb + (tg0 + 2) * SEG_N] = min(base2, SEGCAP);
        if (tg0 + 3 < T_DIM) g_cnt[cb + (tg0 + 3) * SEG_N] = min(base3, SEGCAP);
    }
}

// ---------------------------------------------------------------------------
// g1: layer-1 gather-sum GEMM, split-K x4, LDG.64 gathers.
//     256 threads (208 active), thread owns o-pair {2*tid, 2*tid+1}.
// ---------------------------------------------------------------------------
__global__ void __launch_bounds__(256) g1_kernel() {
    int col = blockIdx.x;
    int q   = blockIdx.y;
    int n = col / T_DIM, t = col % T_DIM;
    int tid = threadIdx.x;

    __shared__ unsigned int sofs[640];
    __shared__ int soff[SEG_N + 1];

    if (tid < 32) {
        int lane = tid;
        int c = g_cnt[col * SEG_N + lane];
        #pragma unroll
        for (int d = 1; d < 32; d <<= 1) {
            int v = __shfl_up_sync(0xffffffffu, c, d);
            if (lane >= d) c += v;
        }
        soff[lane + 1] = c;
        if (lane == 0) soff[0] = 0;
    }
    __syncthreads();

    int cnt = soff[SEG_N];
    int k0 = (cnt * q) / SPLIT;
    int k1 = (cnt * (q + 1)) / SPLIT;
    int M  = k1 - k0;

    for (int s = 0; s < SEG_N; ++s) {
        int sb = soff[s], se_ = soff[s + 1];
        int lo = sb > k0 ? sb : k0;
        int hi = se_ < k1 ? se_ : k1;
        for (int k = lo + tid; k < hi; k += 256)
            sofs[k - k0] = g_idx[(size_t)col * IDX_CAP + s * SEGCAP + (k - sb)];
    }
    __syncthreads();

    if (tid < 208) {
        const char* wbase = reinterpret_cast<const char*>(g_w1t)
                          + (size_t)tid * 8;
        float2 c0 = make_float2(0.f, 0.f);
        float2 c1 = make_float2(0.f, 0.f);
        float2 c2 = make_float2(0.f, 0.f);
        float2 c3 = make_float2(0.f, 0.f);
        #define ACC2(C, A)                                  \
            C.x = __fmaf_rn(A.x, 1.0f, C.x);                \
            C.y = __fmaf_rn(A.y, 1.0f, C.y);
        int m = 0;
        for (; m + 8 <= M; m += 8) {
            uint4 of0 = *reinterpret_cast<const uint4*>(&sofs[m]);
            uint4 of1 = *reinterpret_cast<const uint4*>(&sofs[m + 4]);
            float2 a0 = *reinterpret_cast<const float2*>(wbase + of0.x);
            float2 a1 = *reinterpret_cast<const float2*>(wbase + of0.y);
            float2 a2 = *reinterpret_cast<const float2*>(wbase + of0.z);
            float2 a3 = *reinterpret_cast<const float2*>(wbase + of0.w);
            float2 a4 = *reinterpret_cast<const float2*>(wbase + of1.x);
            float2 a5 = *reinterpret_cast<const float2*>(wbase + of1.y);
            float2 a6 = *reinterpret_cast<const float2*>(wbase + of1.z);
            float2 a7 = *reinterpret_cast<const float2*>(wbase + of1.w);
            ACC2(c0, a0) ACC2(c1, a1) ACC2(c2, a2) ACC2(c3, a3)
            ACC2(c0, a4) ACC2(c1, a5) ACC2(c2, a6) ACC2(c3, a7)
        }
        for (; m < M; ++m) {
            float2 a0 = *reinterpret_cast<const float2*>(wbase + sofs[m]);
            ACC2(c0, a0)
        }
        #undef ACC2
        float2 r;
        r.x = (c0.x + c1.x) + (c2.x + c3.x);
        r.y = (c0.y + c1.y) + (c2.y + c3.y);

        int o0i = tid * 2;
        size_t zb = (size_t)q * ((size_t)N_BATCH * O1 * T_DIM)
                  + ((size_t)n * O1) * T_DIM + t;
        if (o0i + 0 < O1) g_z1p[zb + (size_t)(o0i + 0) * T_DIM] = r.x;
        if (o0i + 1 < O1) g_z1p[zb + (size_t)(o0i + 1) * T_DIM] = r.y;
    }
}

// ---------------------------------------------------------------------------
// l1post: 4-way reduce + FIR + spike scan + s1 store. (r5 version)
// ---------------------------------------------------------------------------
__global__ void __launch_bounds__(128) l1post_kernel() {
    __shared__ float sz[4][T_DIM];
    __shared__ float su[4][T_DIM];
    __shared__ float se[K_FIR];
    int tid = threadIdx.x;
    int row0 = blockIdx.x * 4;
    const size_t PS = (size_t)N_BATCH * O1 * T_DIM;

    if (tid < K_FIR) {
        float a = (float)tid / 10.0f;
        se[tid] = a * expf(1.0f - a);
    }
    for (int task = tid; task < 4 * T_DIM; task += 128) {
        int r = task / T_DIM, tt = task % T_DIM;
        size_t idx = (size_t)(row0 + r) * T_DIM + tt;
        sz[r][tt] = (g_z1p[idx] + g_z1p[idx + PS])
                  + (g_z1p[idx + 2 * PS] + g_z1p[idx + 3 * PS]);
    }
    __syncthreads();

    for (int task = tid; task < 4 * T_DIM; task += 128) {
        int r = task / T_DIM, tt = task % T_DIM;
        int mmax = tt < (K_FIR - 1) ? tt : (K_FIR - 1);
        float a0 = 0.f, a1 = 0.f, a2 = 0.f, a3 = 0.f;
        int m = 1;
        for (; m + 3 <= mmax; m += 4) {
            a0 = fmaf(se[m + 0], sz[r][tt - m - 0], a0);
            a1 = fmaf(se[m + 1], sz[r][tt - m - 1], a1);
            a2 = fmaf(se[m + 2], sz[r][tt - m - 2], a2);
            a3 = fmaf(se[m + 3], sz[r][tt - m - 3], a3);
        }
        for (; m <= mmax; ++m) a0 = fmaf(se[m], sz[r][tt - m], a0);
        su[r][tt] = (a0 + a1) + (a2 + a3);
    }
    __syncthreads();

    if (tid < 4) {
        float p = 0.0f, y = 0.0f;
        for (int t = 0; t < T_DIM; ++t) {
            float ut = su[tid][t];
            y = __fmul_rn(A_REF_F, __fadd_rn(y, __fmul_rn(K_REF_F, p)));
            float sp = (__fadd_rn(ut, y) >= THETA_F) ? 1.0f : 0.0f;
            p = __fadd_rn(__fmul_rn(A_REF_F, p), sp);
            sz[tid][t] = sp;
        }
    }
    __syncthreads();

    for (int task = tid; task < 4 * T_DIM; task += 128) {
        int r = task / T_DIM, tt = task % T_DIM;
        g_s1[(size_t)(row0 + r) * T_DIM + tt] = sz[r][tt];
    }
}

// ---------------------------------------------------------------------------
// g2: layer-2 GEMM, smem-tiled. grid (8, 19), block 160.
// ---------------------------------------------------------------------------
__global__ void g2_kernel(const float* __restrict__ w2) {
    __shared__ float sw[O2 * O1];
    __shared__ float st[O1 * 17];
    int n  = blockIdx.x;
    int t0 = blockIdx.y * 16;
    int tid = threadIdx.x;

    for (int k = tid; k < O2 * O1; k += 160) sw[k] = w2[k];
    for (int k = tid; k < O1 * 16; k += 160) {
        int o = k / 16, tl = k % 16;
        int t = t0 + tl;
        st[o * 17 + tl] = (t < T_DIM)
            ? g_s1[((size_t)n * O1 + o) * T_DIM + t] : 0.0f;
    }
    __syncthreads();

    int tl = tid % 16, o2 = tid / 16;
    int t = t0 + tl;
    if (t < T_DIM) {
        float acc = 0.0f;
        for (int o = 0; o < O1; ++o)
            acc = fmaf(sw[o2 * O1 + o], st[o * 17 + tl], acc);
        g_z2[((size_t)n * O2 + o2) * T_DIM + t] = acc;
    }
}

// ---------------------------------------------------------------------------
// l2post: FIR + spike scan + output store. 80 CTAs.
// ---------------------------------------------------------------------------
__global__ void __launch_bounds__(320) l2post_kernel(float* __restrict__ out) {
    __shared__ float sz[T_DIM];
    __shared__ float su[T_DIM];
    __shared__ float se[K_FIR];
    int row = blockIdx.x;
    int tid = threadIdx.x;

    if (tid < T_DIM) sz[tid] = g_z2[(size_t)row * T_DIM + tid];
    if (tid < K_FIR) {
        float a = (float)tid / 10.0f;
        se[tid] = a * expf(1.0f - a);
    }
    __syncthreads();

    if (tid < T_DIM) {
        int mmax = tid < (K_FIR - 1) ? tid : (K_FIR - 1);
        float a0 = 0.f, a1 = 0.f, a2 = 0.f, a3 = 0.f;
        int m = 1;
        for (; m + 3 <= mmax; m += 4) {
            a0 = fmaf(se[m + 0], sz[tid - m - 0], a0);
            a1 = fmaf(se[m + 1], sz[tid - m - 1], a1);
            a2 = fmaf(se[m + 2], sz[tid - m - 2], a2);
            a3 = fmaf(se[m + 3], sz[tid - m - 3], a3);
        }
        for (; m <= mmax; ++m) a0 = fmaf(se[m], sz[tid - m], a0);
        su[tid] = (a0 + a1) + (a2 + a3);
    }
    __syncthreads();

    if (tid == 0) {
        float p = 0.0f, y = 0.0f;
        for (int t = 0; t < T_DIM; ++t) {
            float ut = su[t];
            y = __fmul_rn(A_REF_F, __fadd_rn(y, __fmul_rn(K_REF_F, p)));
            float sp = (__fadd_rn(ut, y) >= THETA_F) ? 1.0f : 0.0f;
            p = __fadd_rn(__fmul_rn(A_REF_F, p), sp);
            sz[t] = sp;
        }
    }
    __syncthreads();

    if (tid < T_DIM)
        out[(size_t)row * T_DIM + tid] = sz[tid];
}

// ---------------------------------------------------------------------------
extern "C" void kernel_launch(void* const* d_in, const int* in_sizes, int n_in,
                              void* d_out, int out_size) {
    const float* x  = (const float*)d_in[0];
    const float* w1 = (const float*)d_in[1];
    const float* w2 = (const float*)d_in[2];
    float* out = (float*)d_out;

    pre_kernel<<<CPT_CTAS + W1T_CTAS, 256>>>(x, w1);                     // 0
    noop_kernel<<<1, 32>>>();                                            // 1
    noop_kernel<<<1, 32>>>();                                            // 2
    g1_kernel<<<dim3(NCOLS, SPLIT), 256>>>();                            // 3 (ncu)
    l1post_kernel<<<(N_BATCH * O1) / 4, 128>>>();                        // 4
    g2_kernel<<<dim3(N_BATCH, (T_DIM + 15) / 16), 160>>>(w2);            // 5
    l2post_kernel<<<N_BATCH * O2, 320>>>(out);                           // 6
}